// round 12
// baseline (speedup 1.0000x reference)
#include <cuda_runtime.h>
#include <cuda_fp16.h>
#include <cstdint>
#include <math.h>

#define BSZ 2
#define SEQ 2048
#define EMB 2048
#define NH  16
#define HD  128
#define E3  (3*EMB)
#define ROWS (BSZ*SEQ)
#define SCALE 0.08838834764831845f
#define NPERS 296    // 148 SMs x 2 CTAs

// ---------------- static device scratch (no allocations) ------------------
__device__ __half g_hid_hi[(size_t)ROWS * EMB];
__device__ __half g_qkv_hi[(size_t)ROWS * E3];
__device__ __half g_qkv_lo[(size_t)ROWS * E3];
__device__ __half g_attn_hi[(size_t)ROWS * EMB];
__device__ __half g_wfT_hi[(size_t)E3 * EMB];
__device__ __half g_wpT_hi[(size_t)EMB * EMB];
__device__ __half g_vt_hi[(size_t)BSZ * NH * HD * SEQ];
__device__ __half g_p_hi[(size_t)BSZ * NH * SEQ * SEQ];

// ---------------- tile geometries -----------------------------------------
// split path (scores): KC=32, rows 128 x 40 fp16, 256 threads
#define T32STR 40
#define T32B   (128 * T32STR * 2)      // 10240 B
#define SPLIT_STAGE (3 * T32B)         // 30720 B
#define SM_SPLIT (3 * SPLIT_STAGE)     // 92160 B -> 2 CTAs/SM
// single path (qkv/pv/proj): KC=64, rows 128 x 72 fp16, 256 threads
#define T64STR 72
#define T64B   (128 * T64STR * 2)      // 18432 B
#define SNG_STAGE (2 * T64B)           // 36864 B
#define SM_SNG (3 * SNG_STAGE)         // 110592 B -> 2 CTAs/SM

__device__ __forceinline__ uint32_t smem_u32(const void* p) {
    uint32_t a;
    asm("{ .reg .u64 t; cvta.to.shared.u64 t, %1; cvt.u32.u64 %0, t; }"
        : "=r"(a) : "l"(p));
    return a;
}
__device__ __forceinline__ void cpa16(uint32_t d, const void* s) {
    asm volatile("cp.async.cg.shared.global [%0], [%1], 16;" :: "r"(d), "l"(s) : "memory");
}
#define CP_COMMIT() asm volatile("cp.async.commit_group;" ::: "memory")
#define CP_WAIT1()  asm volatile("cp.async.wait_group 1;" ::: "memory")

#define LDMX4(r, a)                                                          \
    asm volatile("ldmatrix.sync.aligned.m8n8.x4.shared.b16 {%0,%1,%2,%3}, [%4];" \
                 : "=r"((r)[0]), "=r"((r)[1]), "=r"((r)[2]), "=r"((r)[3]) : "r"(a))

#define MMA16816(d, a, b0v, b1v)                                             \
    asm volatile("mma.sync.aligned.m16n8k16.row.col.f32.f16.f16.f32 "        \
                 "{%0,%1,%2,%3}, {%4,%5,%6,%7}, {%8,%9}, {%0,%1,%2,%3};"     \
                 : "+f"((d)[0]), "+f"((d)[1]), "+f"((d)[2]), "+f"((d)[3])    \
                 : "r"((a)[0]), "r"((a)[1]), "r"((a)[2]), "r"((a)[3]),       \
                   "r"(b0v), "r"(b1v))

__device__ __forceinline__ void split_pair_h(float x, float y,
                                             uint32_t& hi, uint32_t& lo) {
    __half hx = __float2half_rn(x), hy = __float2half_rn(y);
    __half lx = __float2half_rn(x - __half2float(hx));
    __half ly = __float2half_rn(y - __half2float(hy));
    __half2 H = __halves2half2(hx, hy), L = __halves2half2(lx, ly);
    hi = *reinterpret_cast<uint32_t*>(&H);
    lo = *reinterpret_cast<uint32_t*>(&L);
}
__device__ __forceinline__ uint32_t round_pair_h(float x, float y) {
    __half2 H = __floats2half2_rn(x, y);
    return *reinterpret_cast<uint32_t*>(&H);
}

#define ACC_CLEAR(acc)                                                       \
    _Pragma("unroll") for (int i = 0; i < 2; i++)                            \
    _Pragma("unroll") for (int j = 0; j < 8; j++)                            \
    _Pragma("unroll") for (int q = 0; q < 4; q++) (acc)[i][j][q] = 0.0f;

// ======================= split-A path (scores) =============================
__device__ __forceinline__ void issue32(const __half* __restrict__ ah,
                                        const __half* __restrict__ al, int lda,
                                        const __half* __restrict__ bh, int ldb,
                                        uint32_t stage, int tid) {
#pragma unroll
    for (int i = 0; i < 2; i++) {
        int f = tid + i * 256;
        int r = f >> 2, kg = f & 3;
        uint32_t off = (uint32_t)(r * 80 + kg * 16);
        size_t ga = (size_t)r * lda + kg * 8;
        size_t gb = (size_t)r * ldb + kg * 8;
        cpa16(stage + off, ah + ga);
        cpa16(stage + T32B + off, al + ga);
        cpa16(stage + 2 * T32B + off, bh + gb);
    }
}

__device__ __forceinline__ void mma32(uint32_t st, int warp_m, int warp_n,
                                      int lane, float acc[2][8][4]) {
    const int arow = (lane & 7) + ((lane >> 3) & 1) * 8;
    const int acol = (lane >> 4) * 8;
    const int brow = (lane & 7) + (lane >> 4) * 8;
    const int bcol = ((lane >> 3) & 1) * 8;
#pragma unroll
    for (int k16 = 0; k16 < 2; k16++) {
        const int k0 = k16 * 16;
        uint32_t ah[2][4], al[2][4];
#pragma unroll
        for (int mt = 0; mt < 2; mt++) {
            uint32_t a = st +
                (uint32_t)((warp_m * 32 + mt * 16 + arow) * T32STR + k0 + acol) * 2;
            LDMX4(ah[mt], a);
            LDMX4(al[mt], a + T32B);
        }
#pragma unroll
        for (int np = 0; np < 4; np++) {
            uint32_t b = st + 2 * T32B +
                (uint32_t)((warp_n * 64 + np * 16 + brow) * T32STR + k0 + bcol) * 2;
            uint32_t bh[4];
            LDMX4(bh, b);
#pragma unroll
            for (int mt = 0; mt < 2; mt++) {
                MMA16816(acc[mt][2 * np],     ah[mt], bh[0], bh[1]);
                MMA16816(acc[mt][2 * np + 1], ah[mt], bh[2], bh[3]);
                MMA16816(acc[mt][2 * np],     al[mt], bh[0], bh[1]);
                MMA16816(acc[mt][2 * np + 1], al[mt], bh[2], bh[3]);
            }
        }
    }
}

__device__ __forceinline__ void pipe_split(
    const __half* ah, const __half* al, int lda,
    const __half* bh, int ldb, int nch, uint32_t sb,
    int tid, int warp_m, int warp_n, int lane, float acc[2][8][4])
{
#pragma unroll
    for (int s = 0; s < 2; s++) {
        if (s < nch) issue32(ah + s * 32, al + s * 32, lda, bh + s * 32, ldb,
                             sb + s * SPLIT_STAGE, tid);
        CP_COMMIT();
    }
    for (int c = 0; c < nch; c++) {
        CP_WAIT1();
        __syncthreads();
        mma32(sb + (c % 3) * SPLIT_STAGE, warp_m, warp_n, lane, acc);
        if (c + 2 < nch)
            issue32(ah + (c + 2) * 32, al + (c + 2) * 32, lda,
                    bh + (c + 2) * 32, ldb, sb + ((c + 2) % 3) * SPLIT_STAGE, tid);
        CP_COMMIT();
    }
}

// ======================= single-A path (KC=64, 3-stage) ====================
__device__ __forceinline__ void issue64(const __half* __restrict__ ah, int lda,
                                        const __half* __restrict__ bh, int ldb,
                                        uint32_t stage, int tid) {
#pragma unroll
    for (int i = 0; i < 4; i++) {
        int f = tid + i * 256;
        int r = f >> 3, kg = f & 7;
        uint32_t off = (uint32_t)(r * 144 + kg * 16);
        cpa16(stage + off, ah + (size_t)r * lda + kg * 8);
        cpa16(stage + T64B + off, bh + (size_t)r * ldb + kg * 8);
    }
}

__device__ __forceinline__ void mma64(uint32_t st, int warp_m, int warp_n,
                                      int lane, float acc[2][8][4]) {
    const int arow = (lane & 7) + ((lane >> 3) & 1) * 8;
    const int acol = (lane >> 4) * 8;
    const int brow = (lane & 7) + (lane >> 4) * 8;
    const int bcol = ((lane >> 3) & 1) * 8;
#pragma unroll
    for (int k16 = 0; k16 < 4; k16++) {
        const int k0 = k16 * 16;
        uint32_t ah[2][4];
#pragma unroll
        for (int mt = 0; mt < 2; mt++) {
            uint32_t a = st +
                (uint32_t)((warp_m * 32 + mt * 16 + arow) * T64STR + k0 + acol) * 2;
            LDMX4(ah[mt], a);
        }
#pragma unroll
        for (int np = 0; np < 4; np++) {
            uint32_t b = st + T64B +
                (uint32_t)((warp_n * 64 + np * 16 + brow) * T64STR + k0 + bcol) * 2;
            uint32_t bh[4];
            LDMX4(bh, b);
#pragma unroll
            for (int mt = 0; mt < 2; mt++) {
                MMA16816(acc[mt][2 * np],     ah[mt], bh[0], bh[1]);
                MMA16816(acc[mt][2 * np + 1], ah[mt], bh[2], bh[3]);
            }
        }
    }
}

__device__ __forceinline__ void pipe_single(
    const __half* ah, int lda, const __half* bh, int ldb, int nch, uint32_t sb,
    int tid, int warp_m, int warp_n, int lane, float acc[2][8][4])
{
#pragma unroll
    for (int s = 0; s < 2; s++) {
        if (s < nch) issue64(ah + s * 64, lda, bh + s * 64, ldb,
                             sb + s * SNG_STAGE, tid);
        CP_COMMIT();
    }
    for (int c = 0; c < nch; c++) {
        CP_WAIT1();
        __syncthreads();
        mma64(sb + (c % 3) * SNG_STAGE, warp_m, warp_n, lane, acc);
        if (c + 2 < nch)
            issue64(ah + (c + 2) * 64, lda, bh + (c + 2) * 64, ldb,
                    sb + ((c + 2) % 3) * SNG_STAGE, tid);
        CP_COMMIT();
    }
}

#define GEMM_DECL()                                                          \
    extern __shared__ char smc[];                                            \
    uint32_t sb = smem_u32(smc);                                             \
    const int tid = threadIdx.x;                                             \
    const int wid = tid >> 5, lane = tid & 31;                               \
    const int warp_m = wid & 3, warp_n = wid >> 2;                           \
    float acc[2][8][4];

// ===========================================================================
// qkv: persistent over 48x32 = 1536 tiles. Single-pass fp16.
__global__ __launch_bounds__(256, 2) void gemm_qkv() {
    GEMM_DECL();
    const int g = lane >> 2, t = lane & 3;
    for (int tile = blockIdx.x; tile < 48 * 32; tile += NPERS) {
        const int n0 = (tile % 48) * 128;
        const int m0 = (tile / 48) * 128;
        __syncthreads();               // protect smem reuse across tiles
        ACC_CLEAR(acc);
        pipe_single(g_hid_hi + (size_t)m0 * EMB, EMB,
                    g_wfT_hi + (size_t)n0 * EMB, EMB,
                    EMB / 64, sb, tid, warp_m, warp_n, lane, acc);
        const bool needLo = (n0 < 2 * EMB);
#pragma unroll
        for (int mt = 0; mt < 2; mt++)
#pragma unroll
            for (int nt = 0; nt < 8; nt++) {
                int r = m0 + warp_m * 32 + mt * 16 + g;
                int c = n0 + warp_n * 64 + nt * 8 + t * 2;
                uint32_t h0, l0, h1, l1;
                split_pair_h(acc[mt][nt][0], acc[mt][nt][1], h0, l0);
                split_pair_h(acc[mt][nt][2], acc[mt][nt][3], h1, l1);
                size_t o0 = (size_t)r * E3 + c, o1 = (size_t)(r + 8) * E3 + c;
                *reinterpret_cast<uint32_t*>(g_qkv_hi + o0) = h0;
                *reinterpret_cast<uint32_t*>(g_qkv_hi + o1) = h1;
                if (needLo) {
                    *reinterpret_cast<uint32_t*>(g_qkv_lo + o0) = l0;
                    *reinterpret_cast<uint32_t*>(g_qkv_lo + o1) = l1;
                }
            }
    }
}

// ===========================================================================
// scores: persistent over 32 heads x 136 lower-tri tiles = 4352.
__global__ __launch_bounds__(256, 2) void gemm_scores(float* __restrict__ S) {
    GEMM_DECL();
    const int g = lane >> 2, t = lane & 3;
    const float NEG_INF = __int_as_float(0xff800000);
    for (int tile = blockIdx.x; tile < 32 * 136; tile += NPERS) {
        const int bh2 = tile / 136;
        const int q = tile - bh2 * 136;
        // triangular index: q -> (nq, mq), mq <= nq
        int nq = (int)((sqrtf(8.0f * (float)q + 1.0f) - 1.0f) * 0.5f);
        while ((nq + 1) * (nq + 2) / 2 <= q) nq++;
        while (nq * (nq + 1) / 2 > q) nq--;
        const int mq = q - nq * (nq + 1) / 2;
        const int n0 = nq * 128, m0 = mq * 128;
        const int b = bh2 >> 4, h = bh2 & 15;
        float* out = S + (size_t)bh2 * SEQ * SEQ;
        const size_t qoff = (size_t)b * SEQ * E3 + (size_t)n0 * E3 + h * HD;
        const size_t koff = (size_t)b * SEQ * E3 + (size_t)m0 * E3 + EMB + h * HD;
        __syncthreads();
        ACC_CLEAR(acc);
        pipe_split(g_qkv_hi + qoff, g_qkv_lo + qoff, E3,
                   g_qkv_hi + koff, E3,
                   HD / 32, sb, tid, warp_m, warp_n, lane, acc);
#pragma unroll
        for (int mt = 0; mt < 2; mt++)
#pragma unroll
            for (int nt = 0; nt < 8; nt++) {
                int r = n0 + warp_m * 32 + mt * 16 + g;
                int c = m0 + warp_n * 64 + nt * 8 + t * 2;
                float2 v0, v1;
                v0.x = (c     <= r) ? acc[mt][nt][0] * SCALE : NEG_INF;
                v0.y = (c + 1 <= r) ? acc[mt][nt][1] * SCALE : NEG_INF;
                v1.x = (c     <= r + 8) ? acc[mt][nt][2] * SCALE : NEG_INF;
                v1.y = (c + 1 <= r + 8) ? acc[mt][nt][3] * SCALE : NEG_INF;
                *reinterpret_cast<float2*>(out + (size_t)r * SEQ + c) = v0;
                *reinterpret_cast<float2*>(out + (size_t)(r + 8) * SEQ + c) = v1;
            }
    }
}

// ===========================================================================
// pv: persistent over 16 n-tiles x 32 heads = 512, big tiles first.
__global__ __launch_bounds__(256, 2) void gemm_pv() {
    GEMM_DECL();
    const int g = lane >> 2, t = lane & 3;
    for (int tile = blockIdx.x; tile < 512; tile += NPERS) {
        const int bh2 = tile & 31;
        const int n0 = (15 - (tile >> 5)) * 128;   // largest K first
        const int b = bh2 >> 4, h = bh2 & 15;
        const size_t poff = (size_t)bh2 * SEQ * SEQ + (size_t)n0 * SEQ;
        const size_t voff = (size_t)bh2 * HD * SEQ;
        __syncthreads();
        ACC_CLEAR(acc);
        pipe_single(g_p_hi + poff, SEQ, g_vt_hi + voff, SEQ,
                    (n0 + 128) / 64, sb, tid, warp_m, warp_n, lane, acc);
#pragma unroll
        for (int mt = 0; mt < 2; mt++)
#pragma unroll
            for (int nt = 0; nt < 8; nt++) {
                int r = n0 + warp_m * 32 + mt * 16 + g;
                int c = warp_n * 64 + nt * 8 + t * 2;
                size_t o0 = (size_t)(b * SEQ + r) * EMB + h * HD + c;
                size_t o1 = o0 + (size_t)8 * EMB;
                *reinterpret_cast<uint32_t*>(g_attn_hi + o0) =
                    round_pair_h(acc[mt][nt][0], acc[mt][nt][1]);
                *reinterpret_cast<uint32_t*>(g_attn_hi + o1) =
                    round_pair_h(acc[mt][nt][2], acc[mt][nt][3]);
            }
    }
}

// ===========================================================================
// proj: persistent over 16x32 = 512 tiles. Single-pass fp16 + bias.
__global__ __launch_bounds__(256, 2) void gemm_proj(float* __restrict__ C,
                                                    const float* __restrict__ bias) {
    GEMM_DECL();
    const int g = lane >> 2, t = lane & 3;
    for (int tile = blockIdx.x; tile < 16 * 32; tile += NPERS) {
        const int n0 = (tile % 16) * 128;
        const int m0 = (tile / 16) * 128;
        __syncthreads();
        ACC_CLEAR(acc);
        pipe_single(g_attn_hi + (size_t)m0 * EMB, EMB,
                    g_wpT_hi + (size_t)n0 * EMB, EMB,
                    EMB / 64, sb, tid, warp_m, warp_n, lane, acc);
#pragma unroll
        for (int mt = 0; mt < 2; mt++)
#pragma unroll
            for (int nt = 0; nt < 8; nt++) {
                int r = m0 + warp_m * 32 + mt * 16 + g;
                int c = n0 + warp_n * 64 + nt * 8 + t * 2;
                float2 bv = *reinterpret_cast<const float2*>(bias + c);
                *reinterpret_cast<float2*>(C + (size_t)r * EMB + c) =
                    make_float2(acc[mt][nt][0] + bv.x, acc[mt][nt][1] + bv.y);
                *reinterpret_cast<float2*>(C + (size_t)(r + 8) * EMB + c) =
                    make_float2(acc[mt][nt][2] + bv.x, acc[mt][nt][3] + bv.y);
            }
    }
}

// ===========================================================================
__global__ __launch_bounds__(256) void round_hidden(const float* __restrict__ in) {
    size_t i = ((size_t)blockIdx.x * 256 + threadIdx.x) * 4;
    float4 v = *reinterpret_cast<const float4*>(in + i);
    *reinterpret_cast<uint2*>(g_hid_hi + i) =
        make_uint2(round_pair_h(v.x, v.y), round_pair_h(v.z, v.w));
}

__global__ void transpose_h(const float* __restrict__ in, int rows, int cols,
                            __half* __restrict__ oh) {
    __shared__ float t[32][33];
    int c0 = blockIdx.x * 32, r0 = blockIdx.y * 32;
    int tx = threadIdx.x, ty = threadIdx.y;
#pragma unroll
    for (int j = 0; j < 32; j += 8)
        t[ty + j][tx] = in[(size_t)(r0 + ty + j) * cols + c0 + tx];
    __syncthreads();
#pragma unroll
    for (int j = 0; j < 32; j += 8)
        oh[(size_t)(c0 + ty + j) * rows + r0 + tx] = __float2half_rn(t[tx][ty + j]);
}

__global__ void transpose_v() {
    __shared__ __half th[32][34];
    int bh2 = blockIdx.z, b = bh2 >> 4, h = bh2 & 15;
    const size_t base = (size_t)b * SEQ * E3 + 2 * EMB + h * HD;
    __half* oh = g_vt_hi + (size_t)bh2 * HD * SEQ;
    int c0 = blockIdx.x * 32, r0 = blockIdx.y * 32;
    int tx = threadIdx.x, ty = threadIdx.y;
#pragma unroll
    for (int j = 0; j < 32; j += 8)
        th[ty + j][tx] = g_qkv_hi[base + (size_t)(r0 + ty + j) * E3 + c0 + tx];
    __syncthreads();
#pragma unroll
    for (int j = 0; j < 32; j += 8)
        oh[(size_t)(c0 + ty + j) * SEQ + r0 + tx] = th[tx][ty + j];
}

// ===========================================================================
__global__ __launch_bounds__(256) void softmax_kernel(float* __restrict__ P) {
    const size_t rowi = blockIdx.x;
    const int n = (int)(rowi & (SEQ - 1));
    const int b128 = ((n >> 7) + 1) << 7;
    float* p = P + rowi * SEQ;
    __half* ph = g_p_hi + rowi * SEQ;
    const int tid = threadIdx.x;
    const int c0 = tid * 4, c1 = 1024 + tid * 4;
    const float NEG_INF = __int_as_float(0xff800000);
    float4* p4 = reinterpret_cast<float4*>(p);

    float4 v0 = make_float4(NEG_INF, NEG_INF, NEG_INF, NEG_INF);
    float4 v1 = v0;
    if (c0 < b128) v0 = p4[tid];
    if (c1 < b128) v1 = p4[tid + 256];

    float m = fmaxf(fmaxf(fmaxf(v0.x, v0.y), fmaxf(v0.z, v0.w)),
                    fmaxf(fmaxf(v1.x, v1.y), fmaxf(v1.z, v1.w)));
    __shared__ float red[256];
    red[tid] = m; __syncthreads();
    for (int s = 128; s > 0; s >>= 1) {
        if (tid < s) red[tid] = fmaxf(red[tid], red[tid + s]);
        __syncthreads();
    }
    float rmax = red[0];
    __syncthreads();

    v0.x = __expf(v0.x - rmax); v0.y = __expf(v0.y - rmax);
    v0.z = __expf(v0.z - rmax); v0.w = __expf(v0.w - rmax);
    v1.x = __expf(v1.x - rmax); v1.y = __expf(v1.y - rmax);
    v1.z = __expf(v1.z - rmax); v1.w = __expf(v1.w - rmax);

    float ssum = v0.x + v0.y + v0.z + v0.w + v1.x + v1.y + v1.z + v1.w;
    red[tid] = ssum; __syncthreads();
    for (int s = 128; s > 0; s >>= 1) {
        if (tid < s) red[tid] += red[tid + s];
        __syncthreads();
    }
    float inv = 1.0f / red[0];

    v0.x *= inv; v0.y *= inv; v0.z *= inv; v0.w *= inv;
    v1.x *= inv; v1.y *= inv; v1.z *= inv; v1.w *= inv;
    p4[tid] = v0;
    p4[tid + 256] = v1;

    if (c0 < b128)
        *reinterpret_cast<uint2*>(ph + c0) =
            make_uint2(round_pair_h(v0.x, v0.y), round_pair_h(v0.z, v0.w));
    if (c1 < b128)
        *reinterpret_cast<uint2*>(ph + c1) =
            make_uint2(round_pair_h(v1.x, v1.y), round_pair_h(v1.z, v1.w));
}

// ===========================================================================
extern "C" void kernel_launch(void* const* d_in, const int* in_sizes, int n_in,
                              void* d_out, int out_size)
{
    (void)in_sizes; (void)n_in; (void)out_size;
    const float* hidden  = (const float*)d_in[0];
    const float* w_fused = (const float*)d_in[1];
    const float* w_proj  = (const float*)d_in[2];
    const float* b_proj  = (const float*)d_in[3];

    float* out   = (float*)d_out;
    float* attnw = out + (size_t)ROWS * EMB;

    cudaFuncSetAttribute(gemm_qkv,    cudaFuncAttributeMaxDynamicSharedMemorySize, SM_SNG);
    cudaFuncSetAttribute(gemm_scores, cudaFuncAttributeMaxDynamicSharedMemorySize, SM_SPLIT);
    cudaFuncSetAttribute(gemm_pv,     cudaFuncAttributeMaxDynamicSharedMemorySize, SM_SNG);
    cudaFuncSetAttribute(gemm_proj,   cudaFuncAttributeMaxDynamicSharedMemorySize, SM_SNG);

    __half *wfh, *wph;
    cudaGetSymbolAddress((void**)&wfh, g_wfT_hi);
    cudaGetSymbolAddress((void**)&wph, g_wpT_hi);

    // operand prep
    round_hidden<<<(ROWS * EMB) / 1024, 256>>>(hidden);
    transpose_h<<<dim3(E3 / 32, EMB / 32), dim3(32, 8)>>>(w_fused, EMB, E3, wfh);
    transpose_h<<<dim3(EMB / 32, EMB / 32), dim3(32, 8)>>>(w_proj, EMB, EMB, wph);

    // 1) qkv (persistent)
    gemm_qkv<<<NPERS, 256, SM_SNG>>>();

    // V^T per head
    transpose_v<<<dim3(HD / 32, SEQ / 32, BSZ * NH), dim3(32, 8)>>>();

    // 2) scores (persistent, triangular)
    gemm_scores<<<NPERS, 256, SM_SPLIT>>>(attnw);

    // 3) softmax
    softmax_kernel<<<BSZ * NH * SEQ, 256>>>(attnw);

    // 4) attn_out = P @ V (persistent, big-first)
    gemm_pv<<<NPERS, 256, SM_SNG>>>();

    // 5) out = attn_out @ w_proj + b_proj (persistent)
    gemm_proj<<<NPERS, 256, SM_SNG>>>(out, b_proj);
}

// round 13
// speedup vs baseline: 1.0771x; 1.0771x over previous
#include <cuda_runtime.h>
#include <cuda_fp16.h>
#include <cstdint>

#define BSZ 2
#define SEQ 2048
#define EMB 2048
#define NH  16
#define HD  128
#define E3  (3*EMB)
#define ROWS (BSZ*SEQ)
#define SCALE 0.08838834764831845f

// ---------------- static device scratch (no allocations) ------------------
__device__ __half g_hid_hi[(size_t)ROWS * EMB];
__device__ __half g_qkv_hi[(size_t)ROWS * E3];
__device__ __half g_attn_hi[(size_t)ROWS * EMB];
__device__ __half g_wfT_hi[(size_t)E3 * EMB];
__device__ __half g_wpT_hi[(size_t)EMB * EMB];
__device__ __half g_vt_hi[(size_t)BSZ * NH * HD * SEQ];
__device__ __half g_p_hi[(size_t)BSZ * NH * SEQ * SEQ];

// ---------------- tile geometry (all GEMMs single-pass, KC=64) -------------
#define T64STR 72
#define T64B   (128 * T64STR * 2)      // 18432 B
#define SNG_STAGE (2 * T64B)           // A, B = 36864 B
#define SM_SNG (3 * SNG_STAGE)         // 110592 B -> 2 CTAs/SM (221 KB)

__device__ __forceinline__ uint32_t smem_u32(const void* p) {
    uint32_t a;
    asm("{ .reg .u64 t; cvta.to.shared.u64 t, %1; cvt.u32.u64 %0, t; }"
        : "=r"(a) : "l"(p));
    return a;
}
__device__ __forceinline__ void cpa16(uint32_t d, const void* s) {
    asm volatile("cp.async.cg.shared.global [%0], [%1], 16;" :: "r"(d), "l"(s) : "memory");
}
#define CP_COMMIT() asm volatile("cp.async.commit_group;" ::: "memory")
#define CP_WAIT1()  asm volatile("cp.async.wait_group 1;" ::: "memory")

#define LDMX4(r, a)                                                          \
    asm volatile("ldmatrix.sync.aligned.m8n8.x4.shared.b16 {%0,%1,%2,%3}, [%4];" \
                 : "=r"((r)[0]), "=r"((r)[1]), "=r"((r)[2]), "=r"((r)[3]) : "r"(a))

#define MMA16816(d, a, b0v, b1v)                                             \
    asm volatile("mma.sync.aligned.m16n8k16.row.col.f32.f16.f16.f32 "        \
                 "{%0,%1,%2,%3}, {%4,%5,%6,%7}, {%8,%9}, {%0,%1,%2,%3};"     \
                 : "+f"((d)[0]), "+f"((d)[1]), "+f"((d)[2]), "+f"((d)[3])    \
                 : "r"((a)[0]), "r"((a)[1]), "r"((a)[2]), "r"((a)[3]),       \
                   "r"(b0v), "r"(b1v))

__device__ __forceinline__ uint32_t round_pair_h(float x, float y) {
    __half2 H = __floats2half2_rn(x, y);
    return *reinterpret_cast<uint32_t*>(&H);
}

// ======================= single-A path (KC=64, 3-stage) ====================
__device__ __forceinline__ void issue64(const __half* __restrict__ ah, int lda,
                                        const __half* __restrict__ bh, int ldb,
                                        uint32_t stage, int tid) {
#pragma unroll
    for (int i = 0; i < 4; i++) {
        int f = tid + i * 256;               // 0..1023
        int r = f >> 3, kg = f & 7;
        uint32_t off = (uint32_t)(r * 144 + kg * 16);
        cpa16(stage + off, ah + (size_t)r * lda + kg * 8);
        cpa16(stage + T64B + off, bh + (size_t)r * ldb + kg * 8);
    }
}

__device__ __forceinline__ void mma64(uint32_t st, int warp_m, int warp_n,
                                      int lane, float acc[2][8][4]) {
    const int arow = (lane & 7) + ((lane >> 3) & 1) * 8;
    const int acol = (lane >> 4) * 8;
    const int brow = (lane & 7) + (lane >> 4) * 8;
    const int bcol = ((lane >> 3) & 1) * 8;
#pragma unroll
    for (int k16 = 0; k16 < 4; k16++) {
        const int k0 = k16 * 16;
        uint32_t ah[2][4];
#pragma unroll
        for (int mt = 0; mt < 2; mt++) {
            uint32_t a = st +
                (uint32_t)((warp_m * 32 + mt * 16 + arow) * T64STR + k0 + acol) * 2;
            LDMX4(ah[mt], a);
        }
#pragma unroll
        for (int np = 0; np < 4; np++) {
            uint32_t b = st + T64B +
                (uint32_t)((warp_n * 64 + np * 16 + brow) * T64STR + k0 + bcol) * 2;
            uint32_t bh[4];
            LDMX4(bh, b);
#pragma unroll
            for (int mt = 0; mt < 2; mt++) {
                MMA16816(acc[mt][2 * np],     ah[mt], bh[0], bh[1]);
                MMA16816(acc[mt][2 * np + 1], ah[mt], bh[2], bh[3]);
            }
        }
    }
}

__device__ __forceinline__ void pipe_single(
    const __half* ah, int lda, const __half* bh, int ldb, int nch, uint32_t sb,
    int tid, int warp_m, int warp_n, int lane, float acc[2][8][4])
{
#pragma unroll
    for (int s = 0; s < 2; s++) {
        if (s < nch) issue64(ah + s * 64, lda, bh + s * 64, ldb,
                             sb + s * SNG_STAGE, tid);
        CP_COMMIT();
    }
    for (int c = 0; c < nch; c++) {
        CP_WAIT1();
        __syncthreads();
        mma64(sb + (c % 3) * SNG_STAGE, warp_m, warp_n, lane, acc);
        if (c + 2 < nch)
            issue64(ah + (c + 2) * 64, lda, bh + (c + 2) * 64, ldb,
                    sb + ((c + 2) % 3) * SNG_STAGE, tid);
        CP_COMMIT();
    }
}

#define GEMM_DECL()                                                          \
    extern __shared__ char smc[];                                            \
    uint32_t sb = smem_u32(smc);                                             \
    const int tid = threadIdx.x;                                             \
    const int wid = tid >> 5, lane = tid & 31;                               \
    const int warp_m = wid & 3, warp_n = wid >> 2;                           \
    float acc[2][8][4];                                                      \
    _Pragma("unroll") for (int i = 0; i < 2; i++)                            \
    _Pragma("unroll") for (int j = 0; j < 8; j++)                            \
    _Pragma("unroll") for (int q = 0; q < 4; q++) acc[i][j][q] = 0.0f;

// ===========================================================================
// qkv: single-pass fp16; epilogue writes rn fp16 qkv (no lo anywhere).
__global__ __launch_bounds__(256, 2) void gemm_qkv() {
    GEMM_DECL();
    const int m0 = blockIdx.y * 128, n0 = blockIdx.x * 128;
    pipe_single(g_hid_hi + (size_t)m0 * EMB, EMB,
                g_wfT_hi + (size_t)n0 * EMB, EMB,
                EMB / 64, sb, tid, warp_m, warp_n, lane, acc);
    const int g = lane >> 2, t = lane & 3;
#pragma unroll
    for (int mt = 0; mt < 2; mt++)
#pragma unroll
        for (int nt = 0; nt < 8; nt++) {
            int r = m0 + warp_m * 32 + mt * 16 + g;
            int c = n0 + warp_n * 64 + nt * 8 + t * 2;
            size_t o0 = (size_t)r * E3 + c, o1 = (size_t)(r + 8) * E3 + c;
            *reinterpret_cast<uint32_t*>(g_qkv_hi + o0) =
                round_pair_h(acc[mt][nt][0], acc[mt][nt][1]);
            *reinterpret_cast<uint32_t*>(g_qkv_hi + o1) =
                round_pair_h(acc[mt][nt][2], acc[mt][nt][3]);
        }
}

// ===========================================================================
// scores: single-pass fp16 Q x K, lower-triangular tiles only.
__global__ __launch_bounds__(256, 2) void gemm_scores(float* __restrict__ S) {
    const int bh2 = blockIdx.z, b = bh2 >> 4, h = bh2 & 15;
    const int m0 = blockIdx.x * 128;   // key cols
    const int n0 = blockIdx.y * 128;   // query rows
    if (m0 > n0) return;               // fully masked: softmax writes zeros
    GEMM_DECL();
    float* out = S + (size_t)bh2 * SEQ * SEQ;
    const float NEG_INF = __int_as_float(0xff800000);
    const size_t qoff = (size_t)b * SEQ * E3 + (size_t)n0 * E3 + h * HD;
    const size_t koff = (size_t)b * SEQ * E3 + (size_t)m0 * E3 + EMB + h * HD;
    pipe_single(g_qkv_hi + qoff, E3,
                g_qkv_hi + koff, E3,
                HD / 64, sb, tid, warp_m, warp_n, lane, acc);
    const int g = lane >> 2, t = lane & 3;
#pragma unroll
    for (int mt = 0; mt < 2; mt++)
#pragma unroll
        for (int nt = 0; nt < 8; nt++) {
            int r = n0 + warp_m * 32 + mt * 16 + g;
            int c = m0 + warp_n * 64 + nt * 8 + t * 2;
            float2 v0, v1;
            v0.x = (c     <= r) ? acc[mt][nt][0] * SCALE : NEG_INF;
            v0.y = (c + 1 <= r) ? acc[mt][nt][1] * SCALE : NEG_INF;
            v1.x = (c     <= r + 8) ? acc[mt][nt][2] * SCALE : NEG_INF;
            v1.y = (c + 1 <= r + 8) ? acc[mt][nt][3] * SCALE : NEG_INF;
            *reinterpret_cast<float2*>(out + (size_t)r * SEQ + c) = v0;
            *reinterpret_cast<float2*>(out + (size_t)(r + 8) * SEQ + c) = v1;
        }
}

// ===========================================================================
__global__ __launch_bounds__(256, 2) void gemm_pv() {
    GEMM_DECL();
    const int bh2 = blockIdx.z, b = bh2 >> 4, h = bh2 & 15;
    const int n0 = blockIdx.y * 128;
    const size_t poff = (size_t)bh2 * SEQ * SEQ + (size_t)n0 * SEQ;
    const size_t voff = (size_t)bh2 * HD * SEQ;
    pipe_single(g_p_hi + poff, SEQ, g_vt_hi + voff, SEQ,
                (n0 + 128) / 64, sb, tid, warp_m, warp_n, lane, acc);
    const int g = lane >> 2, t = lane & 3;
#pragma unroll
    for (int mt = 0; mt < 2; mt++)
#pragma unroll
        for (int nt = 0; nt < 8; nt++) {
            int r = n0 + warp_m * 32 + mt * 16 + g;
            int c = warp_n * 64 + nt * 8 + t * 2;
            size_t o0 = (size_t)(b * SEQ + r) * EMB + h * HD + c;
            size_t o1 = o0 + (size_t)8 * EMB;
            *reinterpret_cast<uint32_t*>(g_attn_hi + o0) =
                round_pair_h(acc[mt][nt][0], acc[mt][nt][1]);
            *reinterpret_cast<uint32_t*>(g_attn_hi + o1) =
                round_pair_h(acc[mt][nt][2], acc[mt][nt][3]);
        }
}

// ===========================================================================
__global__ __launch_bounds__(256, 2) void gemm_proj(float* __restrict__ C,
                                                    const float* __restrict__ bias) {
    GEMM_DECL();
    const int m0 = blockIdx.y * 128, n0 = blockIdx.x * 128;
    pipe_single(g_attn_hi + (size_t)m0 * EMB, EMB,
                g_wpT_hi + (size_t)n0 * EMB, EMB,
                EMB / 64, sb, tid, warp_m, warp_n, lane, acc);
    const int g = lane >> 2, t = lane & 3;
#pragma unroll
    for (int mt = 0; mt < 2; mt++)
#pragma unroll
        for (int nt = 0; nt < 8; nt++) {
            int r = m0 + warp_m * 32 + mt * 16 + g;
            int c = n0 + warp_n * 64 + nt * 8 + t * 2;
            float2 bv = *reinterpret_cast<const float2*>(bias + c);
            *reinterpret_cast<float2*>(C + (size_t)r * EMB + c) =
                make_float2(acc[mt][nt][0] + bv.x, acc[mt][nt][1] + bv.y);
            *reinterpret_cast<float2*>(C + (size_t)(r + 8) * EMB + c) =
                make_float2(acc[mt][nt][2] + bv.x, acc[mt][nt][3] + bv.y);
        }
}

// ===========================================================================
__global__ __launch_bounds__(256) void round_hidden(const float* __restrict__ in) {
    size_t i = ((size_t)blockIdx.x * 256 + threadIdx.x) * 4;
    float4 v = *reinterpret_cast<const float4*>(in + i);
    *reinterpret_cast<uint2*>(g_hid_hi + i) =
        make_uint2(round_pair_h(v.x, v.y), round_pair_h(v.z, v.w));
}

__global__ void transpose_h(const float* __restrict__ in, int rows, int cols,
                            __half* __restrict__ oh) {
    __shared__ float t[32][33];
    int c0 = blockIdx.x * 32, r0 = blockIdx.y * 32;
    int tx = threadIdx.x, ty = threadIdx.y;
#pragma unroll
    for (int j = 0; j < 32; j += 8)
        t[ty + j][tx] = in[(size_t)(r0 + ty + j) * cols + c0 + tx];
    __syncthreads();
#pragma unroll
    for (int j = 0; j < 32; j += 8)
        oh[(size_t)(c0 + ty + j) * rows + r0 + tx] = __float2half_rn(t[tx][ty + j]);
}

__global__ void transpose_v() {
    __shared__ __half th[32][34];
    int bh2 = blockIdx.z, b = bh2 >> 4, h = bh2 & 15;
    const size_t base = (size_t)b * SEQ * E3 + 2 * EMB + h * HD;
    __half* oh = g_vt_hi + (size_t)bh2 * HD * SEQ;
    int c0 = blockIdx.x * 32, r0 = blockIdx.y * 32;
    int tx = threadIdx.x, ty = threadIdx.y;
#pragma unroll
    for (int j = 0; j < 32; j += 8)
        th[ty + j][tx] = g_qkv_hi[base + (size_t)(r0 + ty + j) * E3 + c0 + tx];
    __syncthreads();
#pragma unroll
    for (int j = 0; j < 32; j += 8)
        oh[(size_t)(c0 + ty + j) * SEQ + r0 + tx] = th[tx][ty + j];
}

// ===========================================================================
__global__ __launch_bounds__(256) void softmax_kernel(float* __restrict__ P) {
    const size_t rowi = blockIdx.x;
    const int n = (int)(rowi & (SEQ - 1));
    const int b128 = ((n >> 7) + 1) << 7;
    float* p = P + rowi * SEQ;
    __half* ph = g_p_hi + rowi * SEQ;
    const int tid = threadIdx.x;
    const int c0 = tid * 4, c1 = 1024 + tid * 4;
    const float NEG_INF = __int_as_float(0xff800000);
    float4* p4 = reinterpret_cast<float4*>(p);

    float4 v0 = make_float4(NEG_INF, NEG_INF, NEG_INF, NEG_INF);
    float4 v1 = v0;
    if (c0 < b128) v0 = p4[tid];
    if (c1 < b128) v1 = p4[tid + 256];

    float m = fmaxf(fmaxf(fmaxf(v0.x, v0.y), fmaxf(v0.z, v0.w)),
                    fmaxf(fmaxf(v1.x, v1.y), fmaxf(v1.z, v1.w)));
    __shared__ float red[256];
    red[tid] = m; __syncthreads();
    for (int s = 128; s > 0; s >>= 1) {
        if (tid < s) red[tid] = fmaxf(red[tid], red[tid + s]);
        __syncthreads();
    }
    float rmax = red[0];
    __syncthreads();

    v0.x = __expf(v0.x - rmax); v0.y = __expf(v0.y - rmax);
    v0.z = __expf(v0.z - rmax); v0.w = __expf(v0.w - rmax);
    v1.x = __expf(v1.x - rmax); v1.y = __expf(v1.y - rmax);
    v1.z = __expf(v1.z - rmax); v1.w = __expf(v1.w - rmax);

    float ssum = v0.x + v0.y + v0.z + v0.w + v1.x + v1.y + v1.z + v1.w;
    red[tid] = ssum; __syncthreads();
    for (int s = 128; s > 0; s >>= 1) {
        if (tid < s) red[tid] += red[tid + s];
        __syncthreads();
    }
    float inv = 1.0f / red[0];

    v0.x *= inv; v0.y *= inv; v0.z *= inv; v0.w *= inv;
    v1.x *= inv; v1.y *= inv; v1.z *= inv; v1.w *= inv;
    p4[tid] = v0;
    p4[tid + 256] = v1;

    if (c0 < b128)
        *reinterpret_cast<uint2*>(ph + c0) =
            make_uint2(round_pair_h(v0.x, v0.y), round_pair_h(v0.z, v0.w));
    if (c1 < b128)
        *reinterpret_cast<uint2*>(ph + c1) =
            make_uint2(round_pair_h(v1.x, v1.y), round_pair_h(v1.z, v1.w));
}

// ===========================================================================
extern "C" void kernel_launch(void* const* d_in, const int* in_sizes, int n_in,
                              void* d_out, int out_size)
{
    (void)in_sizes; (void)n_in; (void)out_size;
    const float* hidden  = (const float*)d_in[0];
    const float* w_fused = (const float*)d_in[1];
    const float* w_proj  = (const float*)d_in[2];
    const float* b_proj  = (const float*)d_in[3];

    float* out   = (float*)d_out;
    float* attnw = out + (size_t)ROWS * EMB;

    cudaFuncSetAttribute(gemm_qkv,    cudaFuncAttributeMaxDynamicSharedMemorySize, SM_SNG);
    cudaFuncSetAttribute(gemm_scores, cudaFuncAttributeMaxDynamicSharedMemorySize, SM_SNG);
    cudaFuncSetAttribute(gemm_pv,     cudaFuncAttributeMaxDynamicSharedMemorySize, SM_SNG);
    cudaFuncSetAttribute(gemm_proj,   cudaFuncAttributeMaxDynamicSharedMemorySize, SM_SNG);

    __half *wfh, *wph;
    cudaGetSymbolAddress((void**)&wfh, g_wfT_hi);
    cudaGetSymbolAddress((void**)&wph, g_wpT_hi);

    // operand prep
    round_hidden<<<(ROWS * EMB) / 1024, 256>>>(hidden);
    transpose_h<<<dim3(E3 / 32, EMB / 32), dim3(32, 8)>>>(w_fused, EMB, E3, wfh);
    transpose_h<<<dim3(EMB / 32, EMB / 32), dim3(32, 8)>>>(w_proj, EMB, EMB, wph);

    // 1) qkv (single-pass fp16, rn-rounded outputs)
    gemm_qkv<<<dim3(E3 / 128, ROWS / 128), 256, SM_SNG>>>();

    // V^T per head
    transpose_v<<<dim3(HD / 32, SEQ / 32, BSZ * NH), dim3(32, 8)>>>();

    // 2) scores (single-pass fp16, lower-triangular tiles only)
    gemm_scores<<<dim3(SEQ / 128, SEQ / 128, BSZ * NH), 256, SM_SNG>>>(attnw);

    // 3) softmax (fp32 out + rn fp16 P)
    softmax_kernel<<<BSZ * NH * SEQ, 256>>>(attnw);

    // 4) attn_out = P @ V (single-pass fp16)
    gemm_pv<<<dim3(1, SEQ / 128, BSZ * NH), 256, SM_SNG>>>();

    // 5) out = attn_out @ w_proj + b_proj (single-pass fp16)
    gemm_proj<<<dim3(EMB / 128, ROWS / 128), 256, SM_SNG>>>(out, b_proj);
}

// round 14
// speedup vs baseline: 1.1137x; 1.0340x over previous
#include <cuda_runtime.h>
#include <cuda_fp16.h>
#include <cstdint>
#include <math.h>

#define BSZ 2
#define SEQ 2048
#define EMB 2048
#define NH  16
#define HD  128
#define E3  (3*EMB)
#define ROWS (BSZ*SEQ)
#define SCALE 0.08838834764831845f

// ---------------- static device scratch (no allocations) ------------------
__device__ __half g_hid_hi[(size_t)ROWS * EMB];
__device__ __half g_qkv_hi[(size_t)ROWS * E3];
__device__ __half g_attn_hi[(size_t)ROWS * EMB];
__device__ __half g_wfT_hi[(size_t)E3 * EMB];
__device__ __half g_wpT_hi[(size_t)EMB * EMB];
__device__ __half g_vt_hi[(size_t)BSZ * NH * HD * SEQ];
__device__ __half g_p_hi[(size_t)BSZ * NH * SEQ * SEQ];

// ---------------- tile geometry (all GEMMs single-pass, KC=64) -------------
#define T64STR 72
#define T64B   (128 * T64STR * 2)      // 18432 B
#define SNG_STAGE (2 * T64B)           // A, B = 36864 B
#define SM_SNG (3 * SNG_STAGE)         // 110592 B -> 2 CTAs/SM (221 KB)

__device__ __forceinline__ uint32_t smem_u32(const void* p) {
    uint32_t a;
    asm("{ .reg .u64 t; cvta.to.shared.u64 t, %1; cvt.u32.u64 %0, t; }"
        : "=r"(a) : "l"(p));
    return a;
}
__device__ __forceinline__ void cpa16(uint32_t d, const void* s) {
    asm volatile("cp.async.cg.shared.global [%0], [%1], 16;" :: "r"(d), "l"(s) : "memory");
}
#define CP_COMMIT() asm volatile("cp.async.commit_group;" ::: "memory")
#define CP_WAIT1()  asm volatile("cp.async.wait_group 1;" ::: "memory")

#define LDMX4(r, a)                                                          \
    asm volatile("ldmatrix.sync.aligned.m8n8.x4.shared.b16 {%0,%1,%2,%3}, [%4];" \
                 : "=r"((r)[0]), "=r"((r)[1]), "=r"((r)[2]), "=r"((r)[3]) : "r"(a))

#define MMA16816(d, a, b0v, b1v)                                             \
    asm volatile("mma.sync.aligned.m16n8k16.row.col.f32.f16.f16.f32 "        \
                 "{%0,%1,%2,%3}, {%4,%5,%6,%7}, {%8,%9}, {%0,%1,%2,%3};"     \
                 : "+f"((d)[0]), "+f"((d)[1]), "+f"((d)[2]), "+f"((d)[3])    \
                 : "r"((a)[0]), "r"((a)[1]), "r"((a)[2]), "r"((a)[3]),       \
                   "r"(b0v), "r"(b1v))

__device__ __forceinline__ uint32_t round_pair_h(float x, float y) {
    __half2 H = __floats2half2_rn(x, y);
    return *reinterpret_cast<uint32_t*>(&H);
}
__device__ __forceinline__ void stcs_f2(float* p, float2 v) {
    asm volatile("st.global.cs.v2.f32 [%0], {%1,%2};" :: "l"(p), "f"(v.x), "f"(v.y) : "memory");
}
__device__ __forceinline__ void stcs_f4(float* p, float4 v) {
    asm volatile("st.global.cs.v4.f32 [%0], {%1,%2,%3,%4};"
                 :: "l"(p), "f"(v.x), "f"(v.y), "f"(v.z), "f"(v.w) : "memory");
}
__device__ __forceinline__ void stcs_u2(void* p, uint2 v) {
    asm volatile("st.global.cs.v2.u32 [%0], {%1,%2};" :: "l"(p), "r"(v.x), "r"(v.y) : "memory");
}
__device__ __forceinline__ float4 ldcs_f4(const float* p) {
    float4 v;
    asm volatile("ld.global.cs.v4.f32 {%0,%1,%2,%3}, [%4];"
                 : "=f"(v.x), "=f"(v.y), "=f"(v.z), "=f"(v.w) : "l"(p));
    return v;
}

// ======================= single-A path (KC=64, 3-stage) ====================
__device__ __forceinline__ void issue64(const __half* __restrict__ ah, int lda,
                                        const __half* __restrict__ bh, int ldb,
                                        uint32_t stage, int tid) {
#pragma unroll
    for (int i = 0; i < 4; i++) {
        int f = tid + i * 256;               // 0..1023
        int r = f >> 3, kg = f & 7;
        uint32_t off = (uint32_t)(r * 144 + kg * 16);
        cpa16(stage + off, ah + (size_t)r * lda + kg * 8);
        cpa16(stage + T64B + off, bh + (size_t)r * ldb + kg * 8);
    }
}

__device__ __forceinline__ void mma64(uint32_t st, int warp_m, int warp_n,
                                      int lane, float acc[2][8][4]) {
    const int arow = (lane & 7) + ((lane >> 3) & 1) * 8;
    const int acol = (lane >> 4) * 8;
    const int brow = (lane & 7) + (lane >> 4) * 8;
    const int bcol = ((lane >> 3) & 1) * 8;
#pragma unroll
    for (int k16 = 0; k16 < 4; k16++) {
        const int k0 = k16 * 16;
        uint32_t ah[2][4];
#pragma unroll
        for (int mt = 0; mt < 2; mt++) {
            uint32_t a = st +
                (uint32_t)((warp_m * 32 + mt * 16 + arow) * T64STR + k0 + acol) * 2;
            LDMX4(ah[mt], a);
        }
#pragma unroll
        for (int np = 0; np < 4; np++) {
            uint32_t b = st + T64B +
                (uint32_t)((warp_n * 64 + np * 16 + brow) * T64STR + k0 + bcol) * 2;
            uint32_t bh[4];
            LDMX4(bh, b);
#pragma unroll
            for (int mt = 0; mt < 2; mt++) {
                MMA16816(acc[mt][2 * np],     ah[mt], bh[0], bh[1]);
                MMA16816(acc[mt][2 * np + 1], ah[mt], bh[2], bh[3]);
            }
        }
    }
}

__device__ __forceinline__ void pipe_single(
    const __half* ah, int lda, const __half* bh, int ldb, int nch, uint32_t sb,
    int tid, int warp_m, int warp_n, int lane, float acc[2][8][4])
{
#pragma unroll
    for (int s = 0; s < 2; s++) {
        if (s < nch) issue64(ah + s * 64, lda, bh + s * 64, ldb,
                             sb + s * SNG_STAGE, tid);
        CP_COMMIT();
    }
    for (int c = 0; c < nch; c++) {
        CP_WAIT1();
        __syncthreads();
        mma64(sb + (c % 3) * SNG_STAGE, warp_m, warp_n, lane, acc);
        if (c + 2 < nch)
            issue64(ah + (c + 2) * 64, lda, bh + (c + 2) * 64, ldb,
                    sb + ((c + 2) % 3) * SNG_STAGE, tid);
        CP_COMMIT();
    }
}

#define GEMM_DECL()                                                          \
    extern __shared__ char smc[];                                            \
    uint32_t sb = smem_u32(smc);                                             \
    const int tid = threadIdx.x;                                             \
    const int wid = tid >> 5, lane = tid & 31;                               \
    const int warp_m = wid & 3, warp_n = wid >> 2;                           \
    float acc[2][8][4];                                                      \
    _Pragma("unroll") for (int i = 0; i < 2; i++)                            \
    _Pragma("unroll") for (int j = 0; j < 8; j++)                            \
    _Pragma("unroll") for (int q = 0; q < 4; q++) acc[i][j][q] = 0.0f;

// ===========================================================================
__global__ __launch_bounds__(256, 2) void gemm_qkv() {
    GEMM_DECL();
    const int m0 = blockIdx.y * 128, n0 = blockIdx.x * 128;
    pipe_single(g_hid_hi + (size_t)m0 * EMB, EMB,
                g_wfT_hi + (size_t)n0 * EMB, EMB,
                EMB / 64, sb, tid, warp_m, warp_n, lane, acc);
    const int g = lane >> 2, t = lane & 3;
#pragma unroll
    for (int mt = 0; mt < 2; mt++)
#pragma unroll
        for (int nt = 0; nt < 8; nt++) {
            int r = m0 + warp_m * 32 + mt * 16 + g;
            int c = n0 + warp_n * 64 + nt * 8 + t * 2;
            size_t o0 = (size_t)r * E3 + c, o1 = (size_t)(r + 8) * E3 + c;
            *reinterpret_cast<uint32_t*>(g_qkv_hi + o0) =
                round_pair_h(acc[mt][nt][0], acc[mt][nt][1]);
            *reinterpret_cast<uint32_t*>(g_qkv_hi + o1) =
                round_pair_h(acc[mt][nt][2], acc[mt][nt][3]);
        }
}

// ===========================================================================
// scores: compact triangular grid (x: 136 tri tiles, z: 32 heads).
__global__ __launch_bounds__(256, 2) void gemm_scores(float* __restrict__ S) {
    const int bh2 = blockIdx.z, b = bh2 >> 4, h = bh2 & 15;
    const int q = blockIdx.x;           // 0..135 lower-tri tile index
    int nq = (int)((sqrtf(8.0f * (float)q + 1.0f) - 1.0f) * 0.5f);
    while ((nq + 1) * (nq + 2) / 2 <= q) nq++;
    while (nq * (nq + 1) / 2 > q) nq--;
    const int mq = q - nq * (nq + 1) / 2;
    const int n0 = nq * 128, m0 = mq * 128;
    GEMM_DECL();
    float* out = S + (size_t)bh2 * SEQ * SEQ;
    const float NEG_INF = __int_as_float(0xff800000);
    const size_t qoff = (size_t)b * SEQ * E3 + (size_t)n0 * E3 + h * HD;
    const size_t koff = (size_t)b * SEQ * E3 + (size_t)m0 * E3 + EMB + h * HD;
    pipe_single(g_qkv_hi + qoff, E3,
                g_qkv_hi + koff, E3,
                HD / 64, sb, tid, warp_m, warp_n, lane, acc);
    const int g = lane >> 2, t = lane & 3;
#pragma unroll
    for (int mt = 0; mt < 2; mt++)
#pragma unroll
        for (int nt = 0; nt < 8; nt++) {
            int r = n0 + warp_m * 32 + mt * 16 + g;
            int c = m0 + warp_n * 64 + nt * 8 + t * 2;
            float2 v0, v1;
            v0.x = (c     <= r) ? acc[mt][nt][0] * SCALE : NEG_INF;
            v0.y = (c + 1 <= r) ? acc[mt][nt][1] * SCALE : NEG_INF;
            v1.x = (c     <= r + 8) ? acc[mt][nt][2] * SCALE : NEG_INF;
            v1.y = (c + 1 <= r + 8) ? acc[mt][nt][3] * SCALE : NEG_INF;
            stcs_f2(out + (size_t)r * SEQ + c, v0);
            stcs_f2(out + (size_t)(r + 8) * SEQ + c, v1);
        }
}

// ===========================================================================
__global__ __launch_bounds__(256, 2) void gemm_pv() {
    GEMM_DECL();
    const int bh2 = blockIdx.z, b = bh2 >> 4, h = bh2 & 15;
    const int n0 = blockIdx.y * 128;
    const size_t poff = (size_t)bh2 * SEQ * SEQ + (size_t)n0 * SEQ;
    const size_t voff = (size_t)bh2 * HD * SEQ;
    pipe_single(g_p_hi + poff, SEQ, g_vt_hi + voff, SEQ,
                (n0 + 128) / 64, sb, tid, warp_m, warp_n, lane, acc);
    const int g = lane >> 2, t = lane & 3;
#pragma unroll
    for (int mt = 0; mt < 2; mt++)
#pragma unroll
        for (int nt = 0; nt < 8; nt++) {
            int r = n0 + warp_m * 32 + mt * 16 + g;
            int c = warp_n * 64 + nt * 8 + t * 2;
            size_t o0 = (size_t)(b * SEQ + r) * EMB + h * HD + c;
            size_t o1 = o0 + (size_t)8 * EMB;
            *reinterpret_cast<uint32_t*>(g_attn_hi + o0) =
                round_pair_h(acc[mt][nt][0], acc[mt][nt][1]);
            *reinterpret_cast<uint32_t*>(g_attn_hi + o1) =
                round_pair_h(acc[mt][nt][2], acc[mt][nt][3]);
        }
}

// ===========================================================================
__global__ __launch_bounds__(256, 2) void gemm_proj(float* __restrict__ C,
                                                    const float* __restrict__ bias) {
    GEMM_DECL();
    const int m0 = blockIdx.y * 128, n0 = blockIdx.x * 128;
    pipe_single(g_attn_hi + (size_t)m0 * EMB, EMB,
                g_wpT_hi + (size_t)n0 * EMB, EMB,
                EMB / 64, sb, tid, warp_m, warp_n, lane, acc);
    const int g = lane >> 2, t = lane & 3;
#pragma unroll
    for (int mt = 0; mt < 2; mt++)
#pragma unroll
        for (int nt = 0; nt < 8; nt++) {
            int r = m0 + warp_m * 32 + mt * 16 + g;
            int c = n0 + warp_n * 64 + nt * 8 + t * 2;
            float2 bv = *reinterpret_cast<const float2*>(bias + c);
            *reinterpret_cast<float2*>(C + (size_t)r * EMB + c) =
                make_float2(acc[mt][nt][0] + bv.x, acc[mt][nt][1] + bv.y);
            *reinterpret_cast<float2*>(C + (size_t)(r + 8) * EMB + c) =
                make_float2(acc[mt][nt][2] + bv.x, acc[mt][nt][3] + bv.y);
        }
}

// ===========================================================================
__global__ __launch_bounds__(256) void round_hidden(const float* __restrict__ in) {
    size_t i = ((size_t)blockIdx.x * 256 + threadIdx.x) * 4;
    float4 v = *reinterpret_cast<const float4*>(in + i);
    *reinterpret_cast<uint2*>(g_hid_hi + i) =
        make_uint2(round_pair_h(v.x, v.y), round_pair_h(v.z, v.w));
}

__global__ void transpose_h(const float* __restrict__ in, int rows, int cols,
                            __half* __restrict__ oh) {
    __shared__ float t[32][33];
    int c0 = blockIdx.x * 32, r0 = blockIdx.y * 32;
    int tx = threadIdx.x, ty = threadIdx.y;
#pragma unroll
    for (int j = 0; j < 32; j += 8)
        t[ty + j][tx] = in[(size_t)(r0 + ty + j) * cols + c0 + tx];
    __syncthreads();
#pragma unroll
    for (int j = 0; j < 32; j += 8)
        oh[(size_t)(c0 + ty + j) * rows + r0 + tx] = __float2half_rn(t[tx][ty + j]);
}

__global__ void transpose_v() {
    __shared__ __half th[32][34];
    int bh2 = blockIdx.z, b = bh2 >> 4, h = bh2 & 15;
    const size_t base = (size_t)b * SEQ * E3 + 2 * EMB + h * HD;
    __half* oh = g_vt_hi + (size_t)bh2 * HD * SEQ;
    int c0 = blockIdx.x * 32, r0 = blockIdx.y * 32;
    int tx = threadIdx.x, ty = threadIdx.y;
#pragma unroll
    for (int j = 0; j < 32; j += 8)
        th[ty + j][tx] = g_qkv_hi[base + (size_t)(r0 + ty + j) * E3 + c0 + tx];
    __syncthreads();
#pragma unroll
    for (int j = 0; j < 32; j += 8)
        oh[(size_t)(c0 + ty + j) * SEQ + r0 + tx] = th[tx][ty + j];
}

// ===========================================================================
// Softmax: shfl reductions (2 barriers), streaming hints.
__global__ __launch_bounds__(256) void softmax_kernel(float* __restrict__ P) {
    const size_t rowi = blockIdx.x;
    const int n = (int)(rowi & (SEQ - 1));
    const int b128 = ((n >> 7) + 1) << 7;
    float* p = P + rowi * SEQ;
    __half* ph = g_p_hi + rowi * SEQ;
    const int tid = threadIdx.x;
    const int lane = tid & 31, wrp = tid >> 5;
    const int c0 = tid * 4, c1 = 1024 + tid * 4;
    const float NEG_INF = __int_as_float(0xff800000);

    float4 v0 = make_float4(NEG_INF, NEG_INF, NEG_INF, NEG_INF);
    float4 v1 = v0;
    if (c0 < b128) v0 = ldcs_f4(p + c0);
    if (c1 < b128) v1 = ldcs_f4(p + c1);

    float m = fmaxf(fmaxf(fmaxf(v0.x, v0.y), fmaxf(v0.z, v0.w)),
                    fmaxf(fmaxf(v1.x, v1.y), fmaxf(v1.z, v1.w)));
#pragma unroll
    for (int o = 16; o; o >>= 1)
        m = fmaxf(m, __shfl_xor_sync(0xFFFFFFFFu, m, o));
    __shared__ float wmax[8], wsum[8];
    if (lane == 0) wmax[wrp] = m;
    __syncthreads();
    float rmax = fmaxf(fmaxf(fmaxf(wmax[0], wmax[1]), fmaxf(wmax[2], wmax[3])),
                       fmaxf(fmaxf(wmax[4], wmax[5]), fmaxf(wmax[6], wmax[7])));

    v0.x = __expf(v0.x - rmax); v0.y = __expf(v0.y - rmax);
    v0.z = __expf(v0.z - rmax); v0.w = __expf(v0.w - rmax);
    v1.x = __expf(v1.x - rmax); v1.y = __expf(v1.y - rmax);
    v1.z = __expf(v1.z - rmax); v1.w = __expf(v1.w - rmax);

    float s = v0.x + v0.y + v0.z + v0.w + v1.x + v1.y + v1.z + v1.w;
#pragma unroll
    for (int o = 16; o; o >>= 1)
        s += __shfl_xor_sync(0xFFFFFFFFu, s, o);
    if (lane == 0) wsum[wrp] = s;
    __syncthreads();
    float inv = 1.0f / (wsum[0] + wsum[1] + wsum[2] + wsum[3] +
                        wsum[4] + wsum[5] + wsum[6] + wsum[7]);

    v0.x *= inv; v0.y *= inv; v0.z *= inv; v0.w *= inv;
    v1.x *= inv; v1.y *= inv; v1.z *= inv; v1.w *= inv;
    stcs_f4(p + c0, v0);
    stcs_f4(p + c1, v1);

    if (c0 < b128)
        stcs_u2(ph + c0, make_uint2(round_pair_h(v0.x, v0.y), round_pair_h(v0.z, v0.w)));
    if (c1 < b128)
        stcs_u2(ph + c1, make_uint2(round_pair_h(v1.x, v1.y), round_pair_h(v1.z, v1.w)));
}

// ===========================================================================
extern "C" void kernel_launch(void* const* d_in, const int* in_sizes, int n_in,
                              void* d_out, int out_size)
{
    (void)in_sizes; (void)n_in; (void)out_size;
    const float* hidden  = (const float*)d_in[0];
    const float* w_fused = (const float*)d_in[1];
    const float* w_proj  = (const float*)d_in[2];
    const float* b_proj  = (const float*)d_in[3];

    float* out   = (float*)d_out;
    float* attnw = out + (size_t)ROWS * EMB;

    cudaFuncSetAttribute(gemm_qkv,    cudaFuncAttributeMaxDynamicSharedMemorySize, SM_SNG);
    cudaFuncSetAttribute(gemm_scores, cudaFuncAttributeMaxDynamicSharedMemorySize, SM_SNG);
    cudaFuncSetAttribute(gemm_pv,     cudaFuncAttributeMaxDynamicSharedMemorySize, SM_SNG);
    cudaFuncSetAttribute(gemm_proj,   cudaFuncAttributeMaxDynamicSharedMemorySize, SM_SNG);

    __half *wfh, *wph;
    cudaGetSymbolAddress((void**)&wfh, g_wfT_hi);
    cudaGetSymbolAddress((void**)&wph, g_wpT_hi);

    // operand prep
    round_hidden<<<(ROWS * EMB) / 1024, 256>>>(hidden);
    transpose_h<<<dim3(E3 / 32, EMB / 32), dim3(32, 8)>>>(w_fused, EMB, E3, wfh);
    transpose_h<<<dim3(EMB / 32, EMB / 32), dim3(32, 8)>>>(w_proj, EMB, EMB, wph);

    // 1) qkv (single-pass fp16)
    gemm_qkv<<<dim3(E3 / 128, ROWS / 128), 256, SM_SNG>>>();

    // V^T per head
    transpose_v<<<dim3(HD / 32, SEQ / 32, BSZ * NH), dim3(32, 8)>>>();

    // 2) scores (compact triangular grid)
    gemm_scores<<<dim3(136, 1, BSZ * NH), 256, SM_SNG>>>(attnw);

    // 3) softmax (shfl reductions, streaming hints)
    softmax_kernel<<<BSZ * NH * SEQ, 256>>>(attnw);

    // 4) attn_out = P @ V
    gemm_pv<<<dim3(1, SEQ / 128, BSZ * NH), 256, SM_SNG>>>();

    // 5) out = attn_out @ w_proj + b_proj
    gemm_proj<<<dim3(EMB / 128, ROWS / 128), 256, SM_SNG>>>(out, b_proj);
}